// round 1
// baseline (speedup 1.0000x reference)
#include <cuda_runtime.h>
#include <cuda_bf16.h>

// MQIF neuron scan: 8192 independent (batch, feature) chains, 4096 sequential
// steps each. One thread per chain; input double-buffered 32 steps deep in
// registers to hide DRAM latency; streaming cache hints everywhere.

#define BATCH 16
#define STEPS 4096
#define FEAT  512
#define UNROLL 32

__global__ __launch_bounds__(64, 1)
void mqif_scan_kernel(const float* __restrict__ in,
                      float* __restrict__ vout,
                      float* __restrict__ sout)
{
    const int idx = blockIdx.x * blockDim.x + threadIdx.x;   // 0..8191
    const int b = idx >> 9;          // / FEAT
    const int f = idx & (FEAT - 1);  // % FEAT

    const float* ip = in   + ((size_t)b * STEPS) * FEAT + f;
    float*       vp = vout + ((size_t)b * (STEPS + 1)) * FEAT + f;
    float*       sp = sout + ((size_t)b * (STEPS + 1)) * FEAT + f;

    // dt/tau_m = 0.05/10 = 0.005 ; dt/tau_u = 0.05/100 = 5e-4
    const float KV = 0.005f;
    const float KU = 5e-4f;

    float v = -60.0f;   // vr
    float u = 0.0f;

    // Prime the double buffer with the first UNROLL inputs.
    float buf[UNROLL];
#pragma unroll
    for (int j = 0; j < UNROLL; j++)
        buf[j] = __ldcs(ip + j * FEAT);

    for (int t0 = 0; t0 < STEPS; t0 += UNROLL) {
        // Prefetch next chunk (predicated off on the last chunk).
        float nbuf[UNROLL];
        const float* ipn = ip + UNROLL * FEAT;
        const bool more = (t0 + UNROLL) < STEPS;
#pragma unroll
        for (int j = 0; j < UNROLL; j++)
            nbuf[j] = more ? __ldcs(ipn + j * FEAT) : 0.0f;

        // Compute current chunk from registers.
#pragma unroll
        for (int j = 0; j < UNROLL; j++) {
            const float it = buf[j];
            const bool fired = (v >= 30.0f);            // v_peak
            const float vvis = fired ? 30.0f : v;

            // quad = a*(v-vr)*(v-vt) = 0.04*(v+60)*(v+40)
            const float quad = 0.04f * (v + 60.0f) * (v + 40.0f);
            const float g    = quad - u + it;
            const float vc   = fmaf(KV, g, v);          // v + dt*dv
            // u + (dt/tau_u)*(b*(v-vr) - u)
            const float uc   = fmaf(KU, fmaf(0.2f, v + 60.0f, -u), u);

            __stcs(vp + j * FEAT, vvis);
            __stcs(sp + j * FEAT, fired ? 1.0f : 0.0f);

            v = fired ? -60.0f : vc;                    // v_reset
            u = fired ? (u + 2.0f) : uc;                // u + d
        }

#pragma unroll
        for (int j = 0; j < UNROLL; j++) buf[j] = nbuf[j];
        ip = ipn;
        vp += UNROLL * FEAT;
        sp += UNROLL * FEAT;
    }

    // Trailing entry t = STEPS: raw final v, spike = (v >= v_peak)
    __stcs(vp, v);
    __stcs(sp, (v >= 30.0f) ? 1.0f : 0.0f);
}

extern "C" void kernel_launch(void* const* d_in, const int* in_sizes, int n_in,
                              void* d_out, int out_size)
{
    const float* in = (const float*)d_in[0];
    float* out = (float*)d_out;
    // Output is (v_trace, spikes) concatenated: each [16, 4097, 512] fp32.
    const size_t half = (size_t)BATCH * (STEPS + 1) * FEAT;
    float* vout = out;
    float* sout = out + half;

    // 8192 chains: 128 CTAs x 64 threads -> 1 warp per SMSP on 128 SMs.
    mqif_scan_kernel<<<128, 64>>>(in, vout, sout);
}